// round 4
// baseline (speedup 1.0000x reference)
#include <cuda_runtime.h>
#include <cuda_bf16.h>
#include <cstdint>

// Problem constants (fixed by the dataset)
#define NB    16    // batch
#define CC    256   // channels
#define KK    8     // template size
#define MM    63    // input spatial
#define MO    56    // output spatial (63-8+1)
#define BANDS 7     // 7 bands of 8 output rows
#define CSPL  8     // channel splits
#define CPER  32    // channels per block (256/8)
#define OUTSZ (NB * MO * MO)   // 50176

// Channel-split partials: fully rewritten every launch (deterministic, no atomics).
__device__ float g_partial[CSPL * OUTSZ];

// ---------- helpers ----------
__device__ __forceinline__ float fsqrt_approx(float a) {
    float r;
    asm("sqrt.approx.f32 %0, %1;" : "=f"(r) : "f"(a));
    return r;
}

__device__ __forceinline__ unsigned long long pk(float lo, float hi) {
    unsigned long long r;
    asm("mov.b64 %0, {%1, %2};" : "=l"(r)
        : "r"(__float_as_uint(lo)), "r"(__float_as_uint(hi)));
    return r;
}

__device__ __forceinline__ unsigned long long f2fma(unsigned long long a,
                                                    unsigned long long b,
                                                    unsigned long long c) {
    unsigned long long d;
    asm("fma.rn.f32x2 %0, %1, %2, %3;" : "=l"(d) : "l"(a), "l"(b), "l"(c));
    return d;
}

__device__ __forceinline__ void unpk(unsigned long long v, float& lo, float& hi) {
    unsigned int a, b;
    asm("mov.b64 {%0, %1}, %2;" : "=r"(a), "=r"(b) : "l"(v));
    lo = __uint_as_float(a);
    hi = __uint_as_float(b);
}

// Load one sqrt(x) row segment (10 floats = cols base..base+9) as 5 LDS.64 and
// build the 8 overlapping pairs (cols q..q+1 for q=0..7).
__device__ __forceinline__ void loadrow(unsigned long long* d, const float* base) {
    const float2* p2 = reinterpret_cast<const float2*>(base);
    float2 a0 = p2[0], a1 = p2[1], a2 = p2[2], a3 = p2[3], a4 = p2[4];
    d[0] = pk(a0.x, a0.y);
    d[1] = pk(a0.y, a1.x);
    d[2] = pk(a1.x, a1.y);
    d[3] = pk(a1.y, a2.x);
    d[4] = pk(a2.x, a2.y);
    d[5] = pk(a2.y, a3.x);
    d[6] = pk(a3.x, a3.y);
    d[7] = pk(a3.y, a4.x);
}

// ---------- main compute kernel ----------
// grid = NB * BANDS * CSPL = 896 blocks, 64 threads each.
// Block (n, band, cs): output rows [band*8, band*8+8), all 56 cols,
// channels [cs*32, cs*32+32). Writes its partial sum to g_partial[cs].
__global__ __launch_bounds__(64)
void bc_main(const float* __restrict__ z,
             const float* __restrict__ x,
             const float* __restrict__ w) {
    const int bid  = blockIdx.x;
    const int cs   = bid & 7;          // channel split
    const int band = (bid >> 3) % BANDS;
    const int n    = (bid >> 3) / BANDS;
    const int t    = threadIdx.x;

    __shared__ float sx[15][64];                  // sqrt(x) tile, 15 rows x 63 cols (pad 64)
    __shared__ unsigned long long zw2[64];        // splatted (w*sqrt(z)/64) pairs, [p*8+q]

    const int R0 = band * 8;           // first output row of this band
    const int c0 = cs * CPER;

    // Compute-thread coordinates (56 active threads): 28 col-pairs x 2 row-groups.
    const int cp  = t % 28;            // col pair index -> cols 2cp, 2cp+1
    const int rg  = t / 28;            // row group -> local output rows rg*4 .. rg*4+3
    const bool active = (t < 56);
    const int rg4 = rg * 4;
    const int cc2 = 2 * cp;

    unsigned long long acc0 = 0ull, acc1 = 0ull, acc2 = 0ull, acc3 = 0ull;

    for (int c = c0; c < c0 + CPER; ++c) {
        const float* xc = x + (((size_t)(n * CC + c)) * MM + R0) * MM;
        const float* zc = z + ((size_t)(n * CC + c)) * (KK * KK);
        const float  wc = __ldg(w + c) * (1.0f / 64.0f);

        __syncthreads();   // previous iteration's compute done before overwriting tiles

        // Stage sqrt(x): 15 rows x 63 cols (threads 0..62, one element per row each).
        if (t < MM) {
            #pragma unroll
            for (int r = 0; r < 15; ++r)
                sx[r][t] = fsqrt_approx(xc[r * MM + t]);
        }
        // Stage splatted weights: zw2[p*8+q] = (v, v), v = w[c]*sqrt(z[p][q])/64.
        {
            float v = wc * fsqrt_approx(zc[t]);   // t in [0,64)
            zw2[t] = pk(v, v);
        }
        __syncthreads();

        if (active) {
            // Rolling 4-row window of pairs. Slot s holds local sx row == s (mod 4).
            unsigned long long W[4][8];
            loadrow(W[0], &sx[rg4 + 0][cc2]);
            loadrow(W[1], &sx[rg4 + 1][cc2]);
            loadrow(W[2], &sx[rg4 + 2][cc2]);
            #pragma unroll
            for (int p = 0; p < 8; ++p) {
                loadrow(W[(p + 3) & 3], &sx[rg4 + p + 3][cc2]);
                const unsigned long long* zr = &zw2[p * 8];
                #pragma unroll
                for (int q = 0; q < 8; ++q) {
                    const unsigned long long zq = zr[q];   // broadcast LDS.64
                    acc0 = f2fma(W[(p + 0) & 3][q], zq, acc0);
                    acc1 = f2fma(W[(p + 1) & 3][q], zq, acc1);
                    acc2 = f2fma(W[(p + 2) & 3][q], zq, acc2);
                    acc3 = f2fma(W[(p + 3) & 3][q], zq, acc3);
                }
            }
        }
    }

    if (active) {
        float* dst = g_partial + (size_t)cs * OUTSZ + (size_t)n * (MO * MO);
        unsigned long long acc[4] = {acc0, acc1, acc2, acc3};
        #pragma unroll
        for (int rr = 0; rr < 4; ++rr) {
            float lo, hi;
            unpk(acc[rr], lo, hi);
            const int row = R0 + rg4 + rr;
            dst[row * MO + cc2]     = lo;
            dst[row * MO + cc2 + 1] = hi;
        }
    }
}

// ---------- reduction kernel: sum the 8 channel-split partials ----------
__global__ void bc_reduce(float* __restrict__ out) {
    const int i = blockIdx.x * blockDim.x + threadIdx.x;
    if (i < OUTSZ) {
        float s = 0.0f;
        #pragma unroll
        for (int k = 0; k < CSPL; ++k)
            s += g_partial[(size_t)k * OUTSZ + i];
        out[i] = s;
    }
}

// ---------- launch ----------
extern "C" void kernel_launch(void* const* d_in, const int* in_sizes, int n_in,
                              void* d_out, int out_size) {
    const float* z = (const float*)d_in[0];   // (16,256,8,8)
    const float* x = (const float*)d_in[1];   // (16,256,63,63)
    const float* w = (const float*)d_in[2];   // (1,256,1,1,1) -> 256 floats
    float* out = (float*)d_out;               // (16,1,56,56)

    bc_main<<<NB * BANDS * CSPL, 64>>>(z, x, w);
    bc_reduce<<<(OUTSZ + 255) / 256, 256>>>(out);
}